// round 8
// baseline (speedup 1.0000x reference)
#include <cuda_runtime.h>
#include <cstdint>

#define NTOK 25
#define DIM  128
#define NH   4
#define NWIN 64
#define WSQ  49

typedef unsigned long long u64t;

// Weight fragments, tf32-converted, B-frag order (float4 = 2 k-steps).
__device__ float4 g_bqkv[48 * 8 * 32];   // [nt(48)][ks2(8)][lane(32)]
__device__ float4 g_bproj[16 * 8 * 32];  // [nt(16)][ks2(8)][lane(32)]
// Precomputed bias+mask: [w][h][m][n]  (n innermost for coalesced lane reads)
__device__ float g_bm[NWIN * NH * NTOK * NTOK];

__device__ __forceinline__ uint32_t to_tf32(float f) {
    uint32_t u; asm("cvt.rna.tf32.f32 %0, %1;" : "=r"(u) : "f"(f)); return u;
}
__device__ __forceinline__ float tf32f(float f) { return __uint_as_float(to_tf32(f)); }

// Single merged prologue: weight fragment packing + bias/mask table.
__global__ void prologue(const float* __restrict__ qkv_w,
                         const float* __restrict__ proj_w,
                         const float* __restrict__ mask,
                         const int*   __restrict__ ids_keep,
                         const float* __restrict__ bias_table,
                         const int*   __restrict__ rel_index)
{
    const int idx = blockIdx.x * 256 + threadIdx.x;
    if (idx < 16384) {
        const int p = idx;
        const int l = p & 31;
        const int ks2 = (p >> 5) & 7;
        if (p < 48 * 8 * 32) {
            const int nt = p >> 8;
            const int n = nt * 8 + (l >> 2);
            const int k = ks2 * 16 + (l & 3);
            const float* wr = qkv_w + n * DIM + k;
            g_bqkv[p] = make_float4(tf32f(wr[0]), tf32f(wr[4]), tf32f(wr[8]), tf32f(wr[12]));
        } else {
            const int q = p - 48 * 8 * 32;
            const int nt = q >> 8;
            const int n = nt * 8 + (l >> 2);
            const int k = ks2 * 16 + (l & 3);
            const float* wr = proj_w + n * DIM + k;
            g_bproj[q] = make_float4(tf32f(wr[0]), tf32f(wr[4]), tf32f(wr[8]), tf32f(wr[12]));
        }
    } else {
        const int j = idx - 16384;
        if (j < NWIN * NH * NTOK * NTOK) {
            const int w = j / (NH * NTOK * NTOK);
            const int rem = j - w * (NH * NTOK * NTOK);
            const int h = rem / (NTOK * NTOK);
            const int r2 = rem - h * (NTOK * NTOK);
            const int m = r2 / NTOK, n = r2 - m * NTOK;
            const int in_ = ids_keep[w * NTOK + n];
            const int im  = ids_keep[w * NTOK + m];
            g_bm[j] = bias_table[rel_index[in_ * WSQ + im] * NH + h]
                    + mask[(w * WSQ + in_) * WSQ + im];
        }
    }
}

#define MMA_TF32(Cv, a0, a1, a2, a3, b0, b1)                          \
    asm("mma.sync.aligned.m16n8k8.row.col.f32.tf32.tf32.f32 "          \
        "{%0,%1,%2,%3}, {%4,%5,%6,%7}, {%8,%9}, {%0,%1,%2,%3};"        \
        : "+f"(Cv[0]), "+f"(Cv[1]), "+f"(Cv[2]), "+f"(Cv[3])           \
        : "r"(a0), "r"(a1), "r"(a2), "r"(a3), "r"(b0), "r"(b1))

__device__ __forceinline__ u64t pack2(float lo, float hi) {
    u64t r; asm("mov.b64 %0, {%1, %2};" : "=l"(r) : "f"(lo), "f"(hi)); return r;
}
__device__ __forceinline__ float2 unpack2(u64t v) {
    float2 r; asm("mov.b64 {%0, %1}, %2;" : "=f"(r.x), "=f"(r.y) : "l"(v)); return r;
}
#define FMA2(d, a, b, c) \
    asm("fma.rn.f32x2 %0, %1, %2, %3;" : "=l"(d) : "l"(a), "l"(b), "l"(c))
#define ADD2(d, a, b) \
    asm("add.rn.f32x2 %0, %1, %2;" : "=l"(d) : "l"(a), "l"(b))

// A-frag address with chunk-XOR swizzle (float index). chunk,l_mma in [0,32), e in [0,4).
__device__ __forceinline__ int af_addr(int chunk, int l_mma, int e) {
    return ((chunk ^ ((l_mma >> 2) & 7)) * 32 + l_mma) * 4 + e;
}

// Shared layout (floats):
//   af   [0, 4096)           A-frags tf32 (chunk-XOR swizzled)
//   qs   [4096, 9216)        q swizzled: [h][row32][40], chunk-XOR by row
//   ks   [9216, 12816)       [h][tok][36]
//   vs   [12816, 16416)      [h][tok][36]  (also P0 staging: 25 x 136 = 3400)
//   at   [16448, 19148)      probs [h*25+n][27]  (27 coprime 32 -> conflict-free)
#define OFF_Q  4096
#define OFF_K  9216
#define OFF_V  12816
#define OFF_AT 16448
#define SM_FLOATS 19148

__global__ __launch_bounds__(256, 2)
void win_attn_kernel(const float* __restrict__ x,
                     const float* __restrict__ qkv_b,
                     const float* __restrict__ proj_b,
                     float* __restrict__ out)
{
    extern __shared__ float sm[];
    float* af = sm;
    float* qs = sm + OFF_Q;
    float* ks = sm + OFF_K;
    float* vs = sm + OFF_V;
    float* at = sm + OFF_AT;
    float* xstg = vs;            // P0 staging, consumed before P1 writes vs

    const int b = blockIdx.x;
    const int w = b & (NWIN - 1);
    const int t = threadIdx.x;
    const int wid = t >> 5, lane = t & 31;
    const int g = lane >> 2, qd = lane & 3;

    // ---- P0a: coalesced load x -> linear staging [row][136] ----
    {
        const float4* xb4 = (const float4*)(x + (size_t)b * (NTOK * DIM));
        #pragma unroll
        for (int i = 0; i < 3; i++) {
            const int e4 = t + 256 * i;
            const int row = e4 >> 5, col4 = e4 & 31;
            *(float4*)(xstg + row * 136 + col4 * 4) = xb4[e4];
        }
        if (t < 32) {
            const int e4 = 768 + t;
            const int row = e4 >> 5, col4 = e4 & 31;
            *(float4*)(xstg + row * 136 + col4 * 4) = xb4[e4];
        }
    }
    __syncthreads();

    // ---- P0b: pack staging -> A-frag layout (tf32, swizzled), rows >= 25 zeroed ----
    #pragma unroll
    for (int i = 0; i < 4; i++) {
        const int pos = t + 256 * i;
        const int l = pos & 31, chunk = pos >> 5;
        const int ksv = chunk & 15, mt = chunk >> 4;
        const int r0 = mt * 16 + (l >> 2);
        const int c0 = ksv * 8 + (l & 3);
        const float* sp = xstg + r0 * 136 + c0;
        const float x0 = sp[0], x2 = sp[4];
        float x1 = 0.f, x3 = 0.f;
        if (r0 + 8 < NTOK) { x1 = sp[8 * 136]; x3 = sp[8 * 136 + 4]; }
        *(float4*)(af + af_addr(chunk, l, 0)) =
            make_float4(tf32f(x0), tf32f(x1), tf32f(x2), tf32f(x3));
    }
    __syncthreads();

    // ---- P1: QKV via tf32 mma. Warp owns 48 cols (6 ntiles) ----
    {
        float C[6][2][4];
        #pragma unroll
        for (int nt = 0; nt < 6; nt++) {
            const int j0 = (wid * 6 + nt) * 8 + qd * 2;
            const float2 bb = *(const float2*)(qkv_b + j0);
            #pragma unroll
            for (int mt = 0; mt < 2; mt++) {
                C[nt][mt][0] = bb.x; C[nt][mt][1] = bb.y;
                C[nt][mt][2] = bb.x; C[nt][mt][3] = bb.y;
            }
        }
        #pragma unroll
        for (int ks2 = 0; ks2 < 8; ks2++) {
            uint32_t A[2][2][4];
            #pragma unroll
            for (int mt = 0; mt < 2; mt++)
                #pragma unroll
                for (int kk = 0; kk < 2; kk++) {
                    const float4 av = *(const float4*)(af + af_addr(mt * 16 + ks2 * 2 + kk, lane, 0));
                    A[mt][kk][0] = __float_as_uint(av.x);
                    A[mt][kk][1] = __float_as_uint(av.y);
                    A[mt][kk][2] = __float_as_uint(av.z);
                    A[mt][kk][3] = __float_as_uint(av.w);
                }
            #pragma unroll
            for (int nt = 0; nt < 6; nt++) {
                const float4 bv = g_bqkv[((wid * 6 + nt) * 8 + ks2) * 32 + lane];
                const uint32_t b0 = __float_as_uint(bv.x), b1 = __float_as_uint(bv.y);
                const uint32_t b2 = __float_as_uint(bv.z), b3 = __float_as_uint(bv.w);
                MMA_TF32(C[nt][0], A[0][0][0], A[0][0][1], A[0][0][2], A[0][0][3], b0, b1);
                MMA_TF32(C[nt][1], A[1][0][0], A[1][0][1], A[1][0][2], A[1][0][3], b0, b1);
                MMA_TF32(C[nt][0], A[0][1][0], A[0][1][1], A[0][1][2], A[0][1][3], b2, b3);
                MMA_TF32(C[nt][1], A[1][1][0], A[1][1][1], A[1][1][2], A[1][1][3], b2, b3);
            }
        }
        const float scaleq = 0.17677669529663687f;
        #pragma unroll
        for (int nt = 0; nt < 6; nt++) {
            const int j0 = (wid * 6 + nt) * 8 + qd * 2;
            const int part = j0 >> 7, h = (j0 >> 5) & 3, d0 = j0 & 31;
            if (part == 0) {
                #pragma unroll
                for (int mt = 0; mt < 2; mt++) {
                    const int row = mt * 16 + g;
                    const int phys = (d0 >> 2) ^ ((row >> 2) & 7);
                    *(float2*)(qs + h * 1280 + row * 40 + phys * 4 + (d0 & 3)) =
                        make_float2(C[nt][mt][0] * scaleq, C[nt][mt][1] * scaleq);
                    const int row2 = row + 8;
                    if (row2 < NTOK) {
                        const int phys2 = (d0 >> 2) ^ ((row2 >> 2) & 7);
                        *(float2*)(qs + h * 1280 + row2 * 40 + phys2 * 4 + (d0 & 3)) =
                            make_float2(C[nt][mt][2] * scaleq, C[nt][mt][3] * scaleq);
                    }
                }
            } else {
                float* base = (part == 1 ? ks : vs) + h * 900 + d0;
                #pragma unroll
                for (int mt = 0; mt < 2; mt++) {
                    const int row = mt * 16 + g;
                    *(float2*)(base + row * 36) = make_float2(C[nt][mt][0], C[nt][mt][1]);
                    if (row + 8 < NTOK)
                        *(float2*)(base + (row + 8) * 36) = make_float2(C[nt][mt][2], C[nt][mt][3]);
                }
            }
        }
    }
    __syncthreads();

    // ---- P2a: scores + softmax (warps 0-3; warp=head, lane=token) -> probs in smem ----
    if (t < 128) {
        const int h = wid, n = lane;
        if (n < NTOK) {
            float r[NTOK];
            const float* bmb = g_bm + ((w * NH + h) * NTOK) * NTOK + n;
            #pragma unroll
            for (int m = 0; m < NTOK; m++) r[m] = bmb[m * NTOK];
            {   // q (swizzled regs) dot k (broadcast rows)
                ulonglong2 q8[8];
                const int swz = (n >> 2) & 7;
                const float* qb = qs + h * 1280 + n * 40;
                #pragma unroll
                for (int p = 0; p < 8; p++)
                    q8[p] = *(const ulonglong2*)(qb + (p ^ swz) * 4);
                #pragma unroll
                for (int m = 0; m < NTOK; m++) {
                    const ulonglong2* kr = (const ulonglong2*)(ks + h * 900 + m * 36);
                    u64t a0 = 0, a1 = 0, a2 = 0, a3 = 0;
                    #pragma unroll
                    for (int p = 0; p < 8; p += 2) {
                        const ulonglong2 kv0 = kr[p];
                        FMA2(a0, q8[p].x, kv0.x, a0);
                        FMA2(a1, q8[p].y, kv0.y, a1);
                        const ulonglong2 kv1 = kr[p + 1];
                        FMA2(a2, q8[p + 1].x, kv1.x, a2);
                        FMA2(a3, q8[p + 1].y, kv1.y, a3);
                    }
                    ADD2(a0, a0, a2);
                    ADD2(a1, a1, a3);
                    ADD2(a0, a0, a1);
                    const float2 u = unpack2(a0);
                    r[m] += u.x + u.y;
                }
            }
            float mx = r[0];
            #pragma unroll
            for (int m = 1; m < NTOK; m++) mx = fmaxf(mx, r[m]);
            float s = 0.f;
            #pragma unroll
            for (int m = 0; m < NTOK; m++) { r[m] = __expf(r[m] - mx); s += r[m]; }
            const float inv = 1.0f / s;
            float* pr = at + (h * NTOK + n) * 27;
            #pragma unroll
            for (int m = 0; m < NTOK; m++) pr[m] = r[m] * inv;
        }
    }
    __syncthreads();

    // ---- P2b: AV split across 200 threads: (h, half, n) each does 16 dims ----
    if (t < 200) {
        const int h = t / 50;
        const int q2 = t - h * 50;
        const int half = q2 / 25;
        const int n = q2 - half * 25;
        const float* pr = at + (h * NTOK + n) * 27;
        u64t o2[8];
        #pragma unroll
        for (int p = 0; p < 8; p++) o2[p] = 0;
        #pragma unroll
        for (int m = 0; m < NTOK; m++) {
            const ulonglong2* vr = (const ulonglong2*)(vs + h * 900 + m * 36 + half * 16);
            const u64t pm = pack2(pr[m], pr[m]);
            #pragma unroll
            for (int p = 0; p < 4; p++) {
                const ulonglong2 vv = vr[p];
                FMA2(o2[2 * p],     vv.x, pm, o2[2 * p]);
                FMA2(o2[2 * p + 1], vv.y, pm, o2[2 * p + 1]);
            }
        }
        const int lrow = (n & 7) * 4;
        const int chnk_row = (n >> 4) * 16;
        const int ebase = (n >> 3) & 1;
        #pragma unroll
        for (int p = 0; p < 8; p++) {
            const float2 u = unpack2(o2[p]);
            const int c0 = h * 32 + half * 16 + 2 * p;
            af[af_addr(chnk_row + (c0 >> 3), lrow + (c0 & 3),
                       ((c0 & 4) >> 1) + ebase)] = tf32f(u.x);
            const int c1 = c0 + 1;
            af[af_addr(chnk_row + (c1 >> 3), lrow + (c1 & 3),
                       ((c1 & 4) >> 1) + ebase)] = tf32f(u.y);
        }
    }
    __syncthreads();

    // ---- P3: proj via tf32 mma. Warp owns 16 cols (2 ntiles) ----
    {
        float C[2][2][4];
        #pragma unroll
        for (int nt2 = 0; nt2 < 2; nt2++) {
            const int j0 = (wid * 2 + nt2) * 8 + qd * 2;
            const float2 bb = *(const float2*)(proj_b + j0);
            #pragma unroll
            for (int mt = 0; mt < 2; mt++) {
                C[nt2][mt][0] = bb.x; C[nt2][mt][1] = bb.y;
                C[nt2][mt][2] = bb.x; C[nt2][mt][3] = bb.y;
            }
        }
        #pragma unroll
        for (int ks2 = 0; ks2 < 8; ks2++) {
            uint32_t A[2][2][4];
            #pragma unroll
            for (int mt = 0; mt < 2; mt++)
                #pragma unroll
                for (int kk = 0; kk < 2; kk++) {
                    const float4 av = *(const float4*)(af + af_addr(mt * 16 + ks2 * 2 + kk, lane, 0));
                    A[mt][kk][0] = __float_as_uint(av.x);
                    A[mt][kk][1] = __float_as_uint(av.y);
                    A[mt][kk][2] = __float_as_uint(av.z);
                    A[mt][kk][3] = __float_as_uint(av.w);
                }
            #pragma unroll
            for (int nt2 = 0; nt2 < 2; nt2++) {
                const float4 bv = g_bproj[((wid * 2 + nt2) * 8 + ks2) * 32 + lane];
                const uint32_t b0 = __float_as_uint(bv.x), b1 = __float_as_uint(bv.y);
                const uint32_t b2 = __float_as_uint(bv.z), b3 = __float_as_uint(bv.w);
                MMA_TF32(C[nt2][0], A[0][0][0], A[0][0][1], A[0][0][2], A[0][0][3], b0, b1);
                MMA_TF32(C[nt2][1], A[1][0][0], A[1][0][1], A[1][0][2], A[1][0][3], b0, b1);
                MMA_TF32(C[nt2][0], A[0][1][0], A[0][1][1], A[0][1][2], A[0][1][3], b2, b3);
                MMA_TF32(C[nt2][1], A[1][1][0], A[1][1][1], A[1][1][2], A[1][1][3], b2, b3);
            }
        }
        float* ob = out + (size_t)b * (NTOK * DIM);
        #pragma unroll
        for (int nt2 = 0; nt2 < 2; nt2++) {
            const int j0 = (wid * 2 + nt2) * 8 + qd * 2;
            #pragma unroll
            for (int mt = 0; mt < 2; mt++) {
                const int row = mt * 16 + g;   // <= 23, always in range
                *(float2*)(ob + row * DIM + j0) = make_float2(C[nt2][mt][0], C[nt2][mt][1]);
                if (row + 8 < NTOK)
                    *(float2*)(ob + (row + 8) * DIM + j0) = make_float2(C[nt2][mt][2], C[nt2][mt][3]);
            }
        }
    }
}

extern "C" void kernel_launch(void* const* d_in, const int* in_sizes, int n_in,
                              void* d_out, int out_size)
{
    const float* x          = (const float*)d_in[0];
    const float* mask       = (const float*)d_in[1];
    const int*   ids_keep   = (const int*)  d_in[2];
    const float* qkv_w      = (const float*)d_in[3];
    const float* qkv_b      = (const float*)d_in[4];
    const float* proj_w     = (const float*)d_in[5];
    const float* proj_b     = (const float*)d_in[6];
    const float* bias_table = (const float*)d_in[7];
    const int*   rel_index  = (const int*)  d_in[8];

    const int total = 16384 + NWIN * NH * NTOK * NTOK;
    prologue<<<(total + 255) / 256, 256>>>(qkv_w, proj_w, mask, ids_keep,
                                           bias_table, rel_index);

    const int smem_bytes = SM_FLOATS * 4;
    cudaFuncSetAttribute(win_attn_kernel,
                         cudaFuncAttributeMaxDynamicSharedMemorySize, smem_bytes);
    win_attn_kernel<<<4096, 256, smem_bytes>>>(x, qkv_b, proj_b, (float*)d_out);
}

// round 9
// speedup vs baseline: 1.1324x; 1.1324x over previous
#include <cuda_runtime.h>
#include <cstdint>

#define NTOK 25
#define DIM  128
#define NH   4
#define NWIN 64
#define WSQ  49

typedef unsigned long long u64t;

// Weight fragments, tf32-converted, B-frag order (float4 = 2 k-steps).
__device__ float4 g_bqkv[48 * 8 * 32];   // [nt(48)][ks2(8)][lane(32)]
__device__ float4 g_bproj[16 * 8 * 32];  // [nt(16)][ks2(8)][lane(32)]
// Precomputed bias+mask: [w][h][m][n]  (n innermost for coalesced lane reads)
__device__ float g_bm[NWIN * NH * NTOK * NTOK];

__device__ __forceinline__ uint32_t to_tf32(float f) {
    uint32_t u; asm("cvt.rna.tf32.f32 %0, %1;" : "=r"(u) : "f"(f)); return u;
}
__device__ __forceinline__ float tf32f(float f) { return __uint_as_float(to_tf32(f)); }

// Single merged prologue: weight fragment packing + bias/mask table.
__global__ void prologue(const float* __restrict__ qkv_w,
                         const float* __restrict__ proj_w,
                         const float* __restrict__ mask,
                         const int*   __restrict__ ids_keep,
                         const float* __restrict__ bias_table,
                         const int*   __restrict__ rel_index)
{
    const int idx = blockIdx.x * 256 + threadIdx.x;
    if (idx < 16384) {
        const int p = idx;
        const int l = p & 31;
        const int ks2 = (p >> 5) & 7;
        if (p < 48 * 8 * 32) {
            const int nt = p >> 8;
            const int n = nt * 8 + (l >> 2);
            const int k = ks2 * 16 + (l & 3);
            const float* wr = qkv_w + n * DIM + k;
            g_bqkv[p] = make_float4(tf32f(wr[0]), tf32f(wr[4]), tf32f(wr[8]), tf32f(wr[12]));
        } else {
            const int q = p - 48 * 8 * 32;
            const int nt = q >> 8;
            const int n = nt * 8 + (l >> 2);
            const int k = ks2 * 16 + (l & 3);
            const float* wr = proj_w + n * DIM + k;
            g_bproj[q] = make_float4(tf32f(wr[0]), tf32f(wr[4]), tf32f(wr[8]), tf32f(wr[12]));
        }
    } else {
        const int j = idx - 16384;
        if (j < NWIN * NH * NTOK * NTOK) {
            const int w = j / (NH * NTOK * NTOK);
            const int rem = j - w * (NH * NTOK * NTOK);
            const int h = rem / (NTOK * NTOK);
            const int r2 = rem - h * (NTOK * NTOK);
            const int m = r2 / NTOK, n = r2 - m * NTOK;
            const int in_ = ids_keep[w * NTOK + n];
            const int im  = ids_keep[w * NTOK + m];
            g_bm[j] = bias_table[rel_index[in_ * WSQ + im] * NH + h]
                    + mask[(w * WSQ + in_) * WSQ + im];
        }
    }
}

#define MMA_TF32(Cv, a0, a1, a2, a3, b0, b1)                          \
    asm("mma.sync.aligned.m16n8k8.row.col.f32.tf32.tf32.f32 "          \
        "{%0,%1,%2,%3}, {%4,%5,%6,%7}, {%8,%9}, {%0,%1,%2,%3};"        \
        : "+f"(Cv[0]), "+f"(Cv[1]), "+f"(Cv[2]), "+f"(Cv[3])           \
        : "r"(a0), "r"(a1), "r"(a2), "r"(a3), "r"(b0), "r"(b1))

__device__ __forceinline__ u64t pack2(float lo, float hi) {
    u64t r; asm("mov.b64 %0, {%1, %2};" : "=l"(r) : "f"(lo), "f"(hi)); return r;
}
__device__ __forceinline__ float2 unpack2(u64t v) {
    float2 r; asm("mov.b64 {%0, %1}, %2;" : "=f"(r.x), "=f"(r.y) : "l"(v)); return r;
}
#define FMA2(d, a, b, c) \
    asm("fma.rn.f32x2 %0, %1, %2, %3;" : "=l"(d) : "l"(a), "l"(b), "l"(c))
#define ADD2(d, a, b) \
    asm("add.rn.f32x2 %0, %1, %2;" : "=l"(d) : "l"(a), "l"(b))

// A-frag address with chunk-XOR swizzle (float index). chunk,l_mma in [0,32), e in [0,4).
__device__ __forceinline__ int af_addr(int chunk, int l_mma, int e) {
    return ((chunk ^ ((l_mma >> 2) & 7)) * 32 + l_mma) * 4 + e;
}

// Shared layout (floats):
//   af   [0, 4096)           A-frags tf32 (chunk-XOR swizzled)
//   qs   [4096, 9216)        q swizzled: [h][row32][40], chunk-XOR by row
//   ks   [9216, 12816)       [h][tok][36]
//   vs   [12816, 16416)      [h][tok][36]  (also P0 staging: 25 x 136 = 3400)
#define OFF_Q  4096
#define OFF_K  9216
#define OFF_V  12816
#define SM_FLOATS 16448

__global__ __launch_bounds__(256, 2)
void win_attn_kernel(const float* __restrict__ x,
                     const float* __restrict__ qkv_b,
                     const float* __restrict__ proj_b,
                     float* __restrict__ out)
{
    extern __shared__ float sm[];
    float* af = sm;
    float* qs = sm + OFF_Q;
    float* ks = sm + OFF_K;
    float* vs = sm + OFF_V;
    float* xstg = vs;            // P0 staging, consumed before P1 writes vs

    const int b = blockIdx.x;
    const int w = b & (NWIN - 1);
    const int t = threadIdx.x;
    const int wid = t >> 5, lane = t & 31;
    const int g = lane >> 2, qd = lane & 3;

    // ---- P0a: coalesced load x -> linear staging [row][136] ----
    {
        const float4* xb4 = (const float4*)(x + (size_t)b * (NTOK * DIM));
        #pragma unroll
        for (int i = 0; i < 3; i++) {
            const int e4 = t + 256 * i;
            const int row = e4 >> 5, col4 = e4 & 31;
            *(float4*)(xstg + row * 136 + col4 * 4) = xb4[e4];
        }
        if (t < 32) {
            const int e4 = 768 + t;
            const int row = e4 >> 5, col4 = e4 & 31;
            *(float4*)(xstg + row * 136 + col4 * 4) = xb4[e4];
        }
    }
    __syncthreads();

    // ---- P0b: pack staging -> A-frag layout (tf32, swizzled), rows >= 25 zeroed ----
    #pragma unroll
    for (int i = 0; i < 4; i++) {
        const int pos = t + 256 * i;
        const int l = pos & 31, chunk = pos >> 5;
        const int ksv = chunk & 15, mt = chunk >> 4;
        const int r0 = mt * 16 + (l >> 2);
        const int c0 = ksv * 8 + (l & 3);
        const float* sp = xstg + r0 * 136 + c0;
        const float x0 = sp[0], x2 = sp[4];
        float x1 = 0.f, x3 = 0.f;
        if (r0 + 8 < NTOK) { x1 = sp[8 * 136]; x3 = sp[8 * 136 + 4]; }
        *(float4*)(af + af_addr(chunk, l, 0)) =
            make_float4(tf32f(x0), tf32f(x1), tf32f(x2), tf32f(x3));
    }
    __syncthreads();

    // ---- P1: QKV via tf32 mma. Warp owns 48 cols (6 ntiles) ----
    {
        float C[6][2][4];
        #pragma unroll
        for (int nt = 0; nt < 6; nt++) {
            const int j0 = (wid * 6 + nt) * 8 + qd * 2;
            const float2 bb = *(const float2*)(qkv_b + j0);
            #pragma unroll
            for (int mt = 0; mt < 2; mt++) {
                C[nt][mt][0] = bb.x; C[nt][mt][1] = bb.y;
                C[nt][mt][2] = bb.x; C[nt][mt][3] = bb.y;
            }
        }
        #pragma unroll
        for (int ks2 = 0; ks2 < 8; ks2++) {
            uint32_t A[2][2][4];
            #pragma unroll
            for (int mt = 0; mt < 2; mt++)
                #pragma unroll
                for (int kk = 0; kk < 2; kk++) {
                    const float4 av = *(const float4*)(af + af_addr(mt * 16 + ks2 * 2 + kk, lane, 0));
                    A[mt][kk][0] = __float_as_uint(av.x);
                    A[mt][kk][1] = __float_as_uint(av.y);
                    A[mt][kk][2] = __float_as_uint(av.z);
                    A[mt][kk][3] = __float_as_uint(av.w);
                }
            #pragma unroll
            for (int nt = 0; nt < 6; nt++) {
                const float4 bv = g_bqkv[((wid * 6 + nt) * 8 + ks2) * 32 + lane];
                const uint32_t b0 = __float_as_uint(bv.x), b1 = __float_as_uint(bv.y);
                const uint32_t b2 = __float_as_uint(bv.z), b3 = __float_as_uint(bv.w);
                MMA_TF32(C[nt][0], A[0][0][0], A[0][0][1], A[0][0][2], A[0][0][3], b0, b1);
                MMA_TF32(C[nt][1], A[1][0][0], A[1][0][1], A[1][0][2], A[1][0][3], b0, b1);
                MMA_TF32(C[nt][0], A[0][1][0], A[0][1][1], A[0][1][2], A[0][1][3], b2, b3);
                MMA_TF32(C[nt][1], A[1][1][0], A[1][1][1], A[1][1][2], A[1][1][3], b2, b3);
            }
        }
        const float scaleq = 0.17677669529663687f;
        #pragma unroll
        for (int nt = 0; nt < 6; nt++) {
            const int j0 = (wid * 6 + nt) * 8 + qd * 2;
            const int part = j0 >> 7, h = (j0 >> 5) & 3, d0 = j0 & 31;
            if (part == 0) {
                #pragma unroll
                for (int mt = 0; mt < 2; mt++) {
                    const int row = mt * 16 + g;
                    const int phys = (d0 >> 2) ^ ((row >> 2) & 7);
                    *(float2*)(qs + h * 1280 + row * 40 + phys * 4 + (d0 & 3)) =
                        make_float2(C[nt][mt][0] * scaleq, C[nt][mt][1] * scaleq);
                    const int row2 = row + 8;
                    if (row2 < NTOK) {
                        const int phys2 = (d0 >> 2) ^ ((row2 >> 2) & 7);
                        *(float2*)(qs + h * 1280 + row2 * 40 + phys2 * 4 + (d0 & 3)) =
                            make_float2(C[nt][mt][2] * scaleq, C[nt][mt][3] * scaleq);
                    }
                }
            } else {
                float* base = (part == 1 ? ks : vs) + h * 900 + d0;
                #pragma unroll
                for (int mt = 0; mt < 2; mt++) {
                    const int row = mt * 16 + g;
                    *(float2*)(base + row * 36) = make_float2(C[nt][mt][0], C[nt][mt][1]);
                    if (row + 8 < NTOK)
                        *(float2*)(base + (row + 8) * 36) = make_float2(C[nt][mt][2], C[nt][mt][3]);
                }
            }
        }
    }
    __syncthreads();

    // ---- P2: attention (warps 0-3; warp=head, lane=token). Output -> af (tf32) ----
    if (t < 128) {
        const int h = wid, n = lane;
        if (n < NTOK) {
            float r[NTOK];
            const float* bmb = g_bm + ((w * NH + h) * NTOK) * NTOK + n;
            #pragma unroll
            for (int m = 0; m < NTOK; m++) r[m] = bmb[m * NTOK];
            {   // scores: q (swizzled regs) dot k (broadcast rows)
                ulonglong2 q8[8];
                const int swz = (n >> 2) & 7;
                const float* qb = qs + h * 1280 + n * 40;
                #pragma unroll
                for (int p = 0; p < 8; p++)
                    q8[p] = *(const ulonglong2*)(qb + (p ^ swz) * 4);
                #pragma unroll
                for (int m = 0; m < NTOK; m++) {
                    const ulonglong2* kr = (const ulonglong2*)(ks + h * 900 + m * 36);
                    u64t a0 = 0, a1 = 0, a2 = 0, a3 = 0;
                    #pragma unroll
                    for (int p = 0; p < 8; p += 2) {
                        const ulonglong2 kv0 = kr[p];
                        FMA2(a0, q8[p].x, kv0.x, a0);
                        FMA2(a1, q8[p].y, kv0.y, a1);
                        const ulonglong2 kv1 = kr[p + 1];
                        FMA2(a2, q8[p + 1].x, kv1.x, a2);
                        FMA2(a3, q8[p + 1].y, kv1.y, a3);
                    }
                    ADD2(a0, a0, a2);
                    ADD2(a1, a1, a3);
                    ADD2(a0, a0, a1);
                    const float2 u = unpack2(a0);
                    r[m] += u.x + u.y;
                }
            }
            // softmax in registers
            float mx = r[0];
            #pragma unroll
            for (int m = 1; m < NTOK; m++) mx = fmaxf(mx, r[m]);
            float s = 0.f;
            #pragma unroll
            for (int m = 0; m < NTOK; m++) { r[m] = __expf(r[m] - mx); s += r[m]; }
            const float inv = 1.0f / s;
            #pragma unroll
            for (int m = 0; m < NTOK; m++) r[m] *= inv;
            // AV in two 16-wide halves; store tf32 to swizzled A-frag layout
            const int lrow = (n & 7) * 4;
            const int chnk_row = (n >> 4) * 16;
            const int ebase = (n >> 3) & 1;
            #pragma unroll
            for (int half = 0; half < 2; half++) {
                u64t o2[8];
                #pragma unroll
                for (int p = 0; p < 8; p++) o2[p] = 0;
                #pragma unroll
                for (int m = 0; m < NTOK; m++) {
                    const ulonglong2* vr =
                        (const ulonglong2*)(vs + h * 900 + m * 36 + half * 16);
                    const u64t pm = pack2(r[m], r[m]);
                    #pragma unroll
                    for (int p = 0; p < 4; p++) {
                        const ulonglong2 vv = vr[p];
                        FMA2(o2[2 * p],     vv.x, pm, o2[2 * p]);
                        FMA2(o2[2 * p + 1], vv.y, pm, o2[2 * p + 1]);
                    }
                }
                #pragma unroll
                for (int p = 0; p < 8; p++) {
                    const float2 u = unpack2(o2[p]);
                    const int c0 = h * 32 + half * 16 + 2 * p;
                    af[af_addr(chnk_row + (c0 >> 3), lrow + (c0 & 3),
                               ((c0 & 4) >> 1) + ebase)] = tf32f(u.x);
                    const int c1 = c0 + 1;
                    af[af_addr(chnk_row + (c1 >> 3), lrow + (c1 & 3),
                               ((c1 & 4) >> 1) + ebase)] = tf32f(u.y);
                }
            }
        }
    }
    __syncthreads();

    // ---- P3: proj via tf32 mma. Warp owns 16 cols (2 ntiles) ----
    {
        float C[2][2][4];
        #pragma unroll
        for (int nt2 = 0; nt2 < 2; nt2++) {
            const int j0 = (wid * 2 + nt2) * 8 + qd * 2;
            const float2 bb = *(const float2*)(proj_b + j0);
            #pragma unroll
            for (int mt = 0; mt < 2; mt++) {
                C[nt2][mt][0] = bb.x; C[nt2][mt][1] = bb.y;
                C[nt2][mt][2] = bb.x; C[nt2][mt][3] = bb.y;
            }
        }
        #pragma unroll
        for (int ks2 = 0; ks2 < 8; ks2++) {
            uint32_t A[2][2][4];
            #pragma unroll
            for (int mt = 0; mt < 2; mt++)
                #pragma unroll
                for (int kk = 0; kk < 2; kk++) {
                    const float4 av = *(const float4*)(af + af_addr(mt * 16 + ks2 * 2 + kk, lane, 0));
                    A[mt][kk][0] = __float_as_uint(av.x);
                    A[mt][kk][1] = __float_as_uint(av.y);
                    A[mt][kk][2] = __float_as_uint(av.z);
                    A[mt][kk][3] = __float_as_uint(av.w);
                }
            #pragma unroll
            for (int nt2 = 0; nt2 < 2; nt2++) {
                const float4 bv = g_bproj[((wid * 2 + nt2) * 8 + ks2) * 32 + lane];
                const uint32_t b0 = __float_as_uint(bv.x), b1 = __float_as_uint(bv.y);
                const uint32_t b2 = __float_as_uint(bv.z), b3 = __float_as_uint(bv.w);
                MMA_TF32(C[nt2][0], A[0][0][0], A[0][0][1], A[0][0][2], A[0][0][3], b0, b1);
                MMA_TF32(C[nt2][1], A[1][0][0], A[1][0][1], A[1][0][2], A[1][0][3], b0, b1);
                MMA_TF32(C[nt2][0], A[0][1][0], A[0][1][1], A[0][1][2], A[0][1][3], b2, b3);
                MMA_TF32(C[nt2][1], A[1][1][0], A[1][1][1], A[1][1][2], A[1][1][3], b2, b3);
            }
        }
        float* ob = out + (size_t)b * (NTOK * DIM);
        #pragma unroll
        for (int nt2 = 0; nt2 < 2; nt2++) {
            const int j0 = (wid * 2 + nt2) * 8 + qd * 2;
            #pragma unroll
            for (int mt = 0; mt < 2; mt++) {
                const int row = mt * 16 + g;   // <= 23, always in range
                *(float2*)(ob + row * DIM + j0) = make_float2(C[nt2][mt][0], C[nt2][mt][1]);
                if (row + 8 < NTOK)
                    *(float2*)(ob + (row + 8) * DIM + j0) = make_float2(C[nt2][mt][2], C[nt2][mt][3]);
            }
        }
    }
}

extern "C" void kernel_launch(void* const* d_in, const int* in_sizes, int n_in,
                              void* d_out, int out_size)
{
    const float* x          = (const float*)d_in[0];
    const float* mask       = (const float*)d_in[1];
    const int*   ids_keep   = (const int*)  d_in[2];
    const float* qkv_w      = (const float*)d_in[3];
    const float* qkv_b      = (const float*)d_in[4];
    const float* proj_w     = (const float*)d_in[5];
    const float* proj_b     = (const float*)d_in[6];
    const float* bias_table = (const float*)d_in[7];
    const int*   rel_index  = (const int*)  d_in[8];

    const int total = 16384 + NWIN * NH * NTOK * NTOK;
    prologue<<<(total + 255) / 256, 256>>>(qkv_w, proj_w, mask, ids_keep,
                                           bias_table, rel_index);

    const int smem_bytes = SM_FLOATS * 4;
    cudaFuncSetAttribute(win_attn_kernel,
                         cudaFuncAttributeMaxDynamicSharedMemorySize, smem_bytes);
    win_attn_kernel<<<4096, 256, smem_bytes>>>(x, qkv_b, proj_b, (float*)d_out);
}

// round 11
// speedup vs baseline: 1.3621x; 1.2028x over previous
#include <cuda_runtime.h>
#include <cstdint>

#define NTOK 25
#define DIM  128
#define NH   4
#define NWIN 64
#define WSQ  49

typedef unsigned long long u64t;

// Weight fragments, tf32-converted, B-frag order (float4 = 2 k-steps).
__device__ float4 g_bqkv[48 * 8 * 32];   // [nt(48)][ks2(8)][lane(32)]
__device__ float4 g_bproj[16 * 8 * 32];  // [nt(16)][ks2(8)][lane(32)]
// Bias+mask in C-fragment order: [w][h][mt(2)][nt(4)][lane(32)][e(4)]
// value at (row n = mt*16 + (l>>2) + 8*(e>>1), col m = nt*8 + 2*(l&3) + (e&1)):
//   m>=25 -> -1e30 (mask pad cols), n>=25 -> 0, else bias+mask.
__device__ float g_bm2[NWIN * NH * 2 * 4 * 32 * 4];

__device__ __forceinline__ uint32_t to_tf32(float f) {
    uint32_t u; asm("cvt.rna.tf32.f32 %0, %1;" : "=r"(u) : "f"(f)); return u;
}
__device__ __forceinline__ float tf32f(float f) { return __uint_as_float(to_tf32(f)); }

// Single merged prologue: weight fragment packing + C-frag bias/mask table.
__global__ void prologue(const float* __restrict__ qkv_w,
                         const float* __restrict__ proj_w,
                         const float* __restrict__ mask,
                         const int*   __restrict__ ids_keep,
                         const float* __restrict__ bias_table,
                         const int*   __restrict__ rel_index)
{
    const int idx = blockIdx.x * 256 + threadIdx.x;
    if (idx < 16384) {
        const int p = idx;
        const int l = p & 31;
        const int ks2 = (p >> 5) & 7;
        if (p < 48 * 8 * 32) {
            const int nt = p >> 8;
            const int n = nt * 8 + (l >> 2);
            const int k = ks2 * 16 + (l & 3);
            const float* wr = qkv_w + n * DIM + k;
            g_bqkv[p] = make_float4(tf32f(wr[0]), tf32f(wr[4]), tf32f(wr[8]), tf32f(wr[12]));
        } else {
            const int q = p - 48 * 8 * 32;
            const int nt = q >> 8;
            const int n = nt * 8 + (l >> 2);
            const int k = ks2 * 16 + (l & 3);
            const float* wr = proj_w + n * DIM + k;
            g_bproj[q] = make_float4(tf32f(wr[0]), tf32f(wr[4]), tf32f(wr[8]), tf32f(wr[12]));
        }
    } else {
        const int f = idx - 16384;
        if (f < NWIN * NH * 2 * 4 * 32 * 4) {
            const int e  = f & 3;
            const int l  = (f >> 2) & 31;
            const int nt = (f >> 7) & 3;
            const int mt = (f >> 9) & 1;
            const int h  = (f >> 10) & 3;
            const int w  = f >> 12;
            const int n = mt * 16 + (l >> 2) + 8 * (e >> 1);
            const int m = nt * 8 + 2 * (l & 3) + (e & 1);
            float v;
            if (m >= NTOK) v = -1e30f;
            else if (n >= NTOK) v = 0.0f;
            else {
                const int in_ = ids_keep[w * NTOK + n];
                const int im  = ids_keep[w * NTOK + m];
                v = bias_table[rel_index[in_ * WSQ + im] * NH + h]
                  + mask[(w * WSQ + in_) * WSQ + im];
            }
            g_bm2[f] = v;
        }
    }
}

#define MMA_TF32(Cv, a0, a1, a2, a3, b0, b1)                          \
    asm("mma.sync.aligned.m16n8k8.row.col.f32.tf32.tf32.f32 "          \
        "{%0,%1,%2,%3}, {%4,%5,%6,%7}, {%8,%9}, {%0,%1,%2,%3};"        \
        : "+f"(Cv[0]), "+f"(Cv[1]), "+f"(Cv[2]), "+f"(Cv[3])           \
        : "r"(a0), "r"(a1), "r"(a2), "r"(a3), "r"(b0), "r"(b1))

// A-frag address with chunk-XOR swizzle (float index). chunk,l_mma in [0,32), e in [0,4).
__device__ __forceinline__ int af_addr(int chunk, int l_mma, int e) {
    return ((chunk ^ ((l_mma >> 2) & 7)) * 32 + l_mma) * 4 + e;
}

// Shared layout (floats):
//   af   [0, 4096)           x / O A-frags tf32 (chunk-XOR swizzled)
//   qf   [4096, 8192)        q A-frags tf32: per h 8 chunks (K=32, M=32)
//   ks   [8192, 12800)       [h][tok32][36]  tf32 values
//   vs   [12800, 17408)      [h][tok32][36]  tf32 values (also P0 staging 25x136=3400)
//   pt   [17408, 21760)      per-warp P tiles [8][16x34]
#define OFF_QF 4096
#define OFF_K  8192
#define OFF_V  12800
#define OFF_PT 17408
#define SM_FLOATS 21760

__global__ __launch_bounds__(256, 2)
void win_attn_kernel(const float* __restrict__ x,
                     const float* __restrict__ qkv_b,
                     const float* __restrict__ proj_b,
                     float* __restrict__ out)
{
    extern __shared__ float sm[];
    float* af = sm;
    float* qf = sm + OFF_QF;
    float* ks = sm + OFF_K;
    float* vs = sm + OFF_V;
    float* pt = sm + OFF_PT;
    float* xstg = vs;            // P0 staging, consumed before P1 writes vs

    const int b = blockIdx.x;
    const int w = b & (NWIN - 1);
    const int t = threadIdx.x;
    const int wid = t >> 5, lane = t & 31;
    const int g = lane >> 2, qd = lane & 3;

    // ---- P0a: coalesced load x -> linear staging [row][136] ----
    {
        const float4* xb4 = (const float4*)(x + (size_t)b * (NTOK * DIM));
        #pragma unroll
        for (int i = 0; i < 3; i++) {
            const int e4 = t + 256 * i;
            const int row = e4 >> 5, col4 = e4 & 31;
            *(float4*)(xstg + row * 136 + col4 * 4) = xb4[e4];
        }
        if (t < 32) {
            const int e4 = 768 + t;
            const int row = e4 >> 5, col4 = e4 & 31;
            *(float4*)(xstg + row * 136 + col4 * 4) = xb4[e4];
        }
    }
    __syncthreads();

    // ---- P0b: pack staging -> A-frag layout (tf32, swizzled), rows >= 25 zeroed ----
    #pragma unroll
    for (int i = 0; i < 4; i++) {
        const int pos = t + 256 * i;
        const int l = pos & 31, chunk = pos >> 5;
        const int ksv = chunk & 15, mt = chunk >> 4;
        const int r0 = mt * 16 + (l >> 2);
        const int c0 = ksv * 8 + (l & 3);
        const float* sp = xstg + r0 * 136 + c0;
        const float x0 = sp[0], x2 = sp[4];
        float x1 = 0.f, x3 = 0.f;
        if (r0 + 8 < NTOK) { x1 = sp[8 * 136]; x3 = sp[8 * 136 + 4]; }
        *(float4*)(af + af_addr(chunk, l, 0)) =
            make_float4(tf32f(x0), tf32f(x1), tf32f(x2), tf32f(x3));
    }
    __syncthreads();

    // ---- P1: QKV via tf32 mma. Warp owns 48 cols (6 ntiles) ----
    {
        float C[6][2][4];
        #pragma unroll
        for (int nt = 0; nt < 6; nt++) {
            const int j0 = (wid * 6 + nt) * 8 + qd * 2;
            const float2 bb = *(const float2*)(qkv_b + j0);
            #pragma unroll
            for (int mt = 0; mt < 2; mt++) {
                C[nt][mt][0] = bb.x; C[nt][mt][1] = bb.y;
                C[nt][mt][2] = bb.x; C[nt][mt][3] = bb.y;
            }
        }
        #pragma unroll
        for (int ks2 = 0; ks2 < 8; ks2++) {
            uint32_t A[2][2][4];
            #pragma unroll
            for (int mt = 0; mt < 2; mt++)
                #pragma unroll
                for (int kk = 0; kk < 2; kk++) {
                    const float4 av = *(const float4*)(af + af_addr(mt * 16 + ks2 * 2 + kk, lane, 0));
                    A[mt][kk][0] = __float_as_uint(av.x);
                    A[mt][kk][1] = __float_as_uint(av.y);
                    A[mt][kk][2] = __float_as_uint(av.z);
                    A[mt][kk][3] = __float_as_uint(av.w);
                }
            #pragma unroll
            for (int nt = 0; nt < 6; nt++) {
                const float4 bv = g_bqkv[((wid * 6 + nt) * 8 + ks2) * 32 + lane];
                const uint32_t b0 = __float_as_uint(bv.x), b1 = __float_as_uint(bv.y);
                const uint32_t b2 = __float_as_uint(bv.z), b3 = __float_as_uint(bv.w);
                MMA_TF32(C[nt][0], A[0][0][0], A[0][0][1], A[0][0][2], A[0][0][3], b0, b1);
                MMA_TF32(C[nt][1], A[1][0][0], A[1][0][1], A[1][0][2], A[1][0][3], b0, b1);
                MMA_TF32(C[nt][0], A[0][1][0], A[0][1][1], A[0][1][2], A[0][1][3], b2, b3);
                MMA_TF32(C[nt][1], A[1][1][0], A[1][1][1], A[1][1][2], A[1][1][3], b2, b3);
            }
        }
        const float scaleq = 0.17677669529663687f;
        #pragma unroll
        for (int nt = 0; nt < 6; nt++) {
            const int j0 = (wid * 6 + nt) * 8 + qd * 2;
            const int part = j0 >> 7, h = (j0 >> 5) & 3, d0 = j0 & 31;
            if (part == 0) {
                // scatter q (pre-scaled, tf32) directly into A-frag layout
                float* qh = qf + h * 1024;
                #pragma unroll
                for (int mt = 0; mt < 2; mt++) {
                    #pragma unroll
                    for (int eb = 0; eb < 2; eb++) {
                        const int col = d0 + eb;
                        const int chunk = mt * 4 + (col >> 3);
                        const int lt = g * 4 + (col & 3);
                        const int e0 = (col & 4) >> 1;
                        *(float2*)(qh + ((chunk ^ ((lt >> 2) & 7)) * 32 + lt) * 4 + e0) =
                            make_float2(tf32f(C[nt][mt][eb] * scaleq),
                                        tf32f(C[nt][mt][2 + eb] * scaleq));
                    }
                }
            } else {
                float* base = (part == 1 ? ks : vs) + h * 1152 + d0;
                #pragma unroll
                for (int mt = 0; mt < 2; mt++) {
                    const int row = mt * 16 + g;
                    *(float2*)(base + row * 36) =
                        make_float2(tf32f(C[nt][mt][0]), tf32f(C[nt][mt][1]));
                    *(float2*)(base + (row + 8) * 36) =
                        make_float2(tf32f(C[nt][mt][2]), tf32f(C[nt][mt][3]));
                }
            }
        }
    }
    __syncthreads();

    // ---- P2: attention via tf32 mma. warp = (h = wid&3, mtw = wid>>2) ----
    {
        const int h = wid & 3;
        const int mtw = wid >> 2;
        const float* qh = qf + h * 1024;
        const float* ksh = ks + h * 1152;
        const float* vsh = vs + h * 1152;
        float* ptw = pt + wid * 544;          // [16][34]

        // q A-frags (conflict-free LDS.128)
        uint32_t Aq[4][4];
        #pragma unroll
        for (int kt = 0; kt < 4; kt++) {
            const int chunk = mtw * 4 + kt;
            const float4 av = *(const float4*)(qh + ((chunk ^ ((lane >> 2) & 7)) * 32 + lane) * 4);
            Aq[kt][0] = __float_as_uint(av.x);
            Aq[kt][1] = __float_as_uint(av.y);
            Aq[kt][2] = __float_as_uint(av.z);
            Aq[kt][3] = __float_as_uint(av.w);
        }
        // S init = bias+mask (C-frag order), then += q @ k^T
        float Sc[4][4];
        {
            const float4* bm2 = (const float4*)g_bm2
                              + (((w * NH + h) * 2 + mtw) * 4) * 32 + lane;
            #pragma unroll
            for (int nt = 0; nt < 4; nt++) {
                const float4 bb = bm2[nt * 32];
                Sc[nt][0] = bb.x; Sc[nt][1] = bb.y; Sc[nt][2] = bb.z; Sc[nt][3] = bb.w;
            }
        }
        #pragma unroll
        for (int nt = 0; nt < 4; nt++) {
            #pragma unroll
            for (int kt = 0; kt < 4; kt++) {
                const uint32_t b0 = __float_as_uint(ksh[(nt * 8 + g) * 36 + kt * 8 + qd]);
                const uint32_t b1 = __float_as_uint(ksh[(nt * 8 + g) * 36 + kt * 8 + qd + 4]);
                MMA_TF32(Sc[nt], Aq[kt][0], Aq[kt][1], Aq[kt][2], Aq[kt][3], b0, b1);
            }
        }
        // softmax over cols for rows (g) and (g+8); reduce across qd group
        float mlo = Sc[0][0], mhi = Sc[0][2];
        #pragma unroll
        for (int nt = 0; nt < 4; nt++) {
            mlo = fmaxf(mlo, fmaxf(Sc[nt][0], Sc[nt][1]));
            mhi = fmaxf(mhi, fmaxf(Sc[nt][2], Sc[nt][3]));
        }
        mlo = fmaxf(mlo, __shfl_xor_sync(0xffffffffu, mlo, 1));
        mlo = fmaxf(mlo, __shfl_xor_sync(0xffffffffu, mlo, 2));
        mhi = fmaxf(mhi, __shfl_xor_sync(0xffffffffu, mhi, 1));
        mhi = fmaxf(mhi, __shfl_xor_sync(0xffffffffu, mhi, 2));
        float slo = 0.f, shi = 0.f;
        #pragma unroll
        for (int nt = 0; nt < 4; nt++) {
            Sc[nt][0] = __expf(Sc[nt][0] - mlo); slo += Sc[nt][0];
            Sc[nt][1] = __expf(Sc[nt][1] - mlo); slo += Sc[nt][1];
            Sc[nt][2] = __expf(Sc[nt][2] - mhi); shi += Sc[nt][2];
            Sc[nt][3] = __expf(Sc[nt][3] - mhi); shi += Sc[nt][3];
        }
        slo += __shfl_xor_sync(0xffffffffu, slo, 1);
        slo += __shfl_xor_sync(0xffffffffu, slo, 2);
        shi += __shfl_xor_sync(0xffffffffu, shi, 1);
        shi += __shfl_xor_sync(0xffffffffu, shi, 2);
        const float ilo = 1.0f / slo, ihi = 1.0f / shi;
        // store P (tf32) to per-warp tile, then reload as A-frags
        #pragma unroll
        for (int nt = 0; nt < 4; nt++) {
            *(float2*)(ptw + g * 34 + nt * 8 + 2 * qd) =
                make_float2(tf32f(Sc[nt][0] * ilo), tf32f(Sc[nt][1] * ilo));
            *(float2*)(ptw + (g + 8) * 34 + nt * 8 + 2 * qd) =
                make_float2(tf32f(Sc[nt][2] * ihi), tf32f(Sc[nt][3] * ihi));
        }
        __syncwarp();
        uint32_t Pa[4][4];
        #pragma unroll
        for (int kt = 0; kt < 4; kt++) {
            Pa[kt][0] = __float_as_uint(ptw[g * 34 + kt * 8 + qd]);
            Pa[kt][1] = __float_as_uint(ptw[(g + 8) * 34 + kt * 8 + qd]);
            Pa[kt][2] = __float_as_uint(ptw[g * 34 + kt * 8 + qd + 4]);
            Pa[kt][3] = __float_as_uint(ptw[(g + 8) * 34 + kt * 8 + qd + 4]);
        }
        // O = P @ V
        float Oc[4][4];
        #pragma unroll
        for (int nt = 0; nt < 4; nt++)
            #pragma unroll
            for (int e = 0; e < 4; e++) Oc[nt][e] = 0.f;
        #pragma unroll
        for (int nt = 0; nt < 4; nt++) {
            #pragma unroll
            for (int kt = 0; kt < 4; kt++) {
                const uint32_t b0 = __float_as_uint(vsh[(kt * 8 + qd) * 36 + nt * 8 + g]);
                const uint32_t b1 = __float_as_uint(vsh[(kt * 8 + qd + 4) * 36 + nt * 8 + g]);
                MMA_TF32(Oc[nt], Pa[kt][0], Pa[kt][1], Pa[kt][2], Pa[kt][3], b0, b1);
            }
        }
        // scatter O (tf32) into af A-frag layout
        #pragma unroll
        for (int nt = 0; nt < 4; nt++) {
            #pragma unroll
            for (int eb = 0; eb < 2; eb++) {
                const int c = h * 32 + nt * 8 + 2 * qd + eb;
                const int chunk = mtw * 16 + (c >> 3);
                const int lt = g * 4 + (c & 3);
                const int e0 = (c & 4) >> 1;
                *(float2*)(af + ((chunk ^ ((lt >> 2) & 7)) * 32 + lt) * 4 + e0) =
                    make_float2(tf32f(Oc[nt][eb]), tf32f(Oc[nt][2 + eb]));
            }
        }
    }
    __syncthreads();

    // ---- P3: proj via tf32 mma. Warp owns 16 cols (2 ntiles) ----
    {
        float C[2][2][4];
        #pragma unroll
        for (int nt2 = 0; nt2 < 2; nt2++) {
            const int j0 = (wid * 2 + nt2) * 8 + qd * 2;
            const float2 bb = *(const float2*)(proj_b + j0);
            #pragma unroll
            for (int mt = 0; mt < 2; mt++) {
                C[nt2][mt][0] = bb.x; C[nt2][mt][1] = bb.y;
                C[nt2][mt][2] = bb.x; C[nt2][mt][3] = bb.y;
            }
        }
        #pragma unroll
        for (int ks2 = 0; ks2 < 8; ks2++) {
            uint32_t A[2][2][4];
            #pragma unroll
            for (int mt = 0; mt < 2; mt++)
                #pragma unroll
                for (int kk = 0; kk < 2; kk++) {
                    const float4 av = *(const float4*)(af + af_addr(mt * 16 + ks2 * 2 + kk, lane, 0));
                    A[mt][kk][0] = __float_as_uint(av.x);
                    A[mt][kk][1] = __float_as_uint(av.y);
                    A[mt][kk][2] = __float_as_uint(av.z);
                    A[mt][kk][3] = __float_as_uint(av.w);
                }
            #pragma unroll
            for (int nt2 = 0; nt2 < 2; nt2++) {
                const float4 bv = g_bproj[((wid * 2 + nt2) * 8 + ks2) * 32 + lane];
                const uint32_t b0 = __float_as_uint(bv.x), b1 = __float_as_uint(bv.y);
                const uint32_t b2 = __float_as_uint(bv.z), b3 = __float_as_uint(bv.w);
                MMA_TF32(C[nt2][0], A[0][0][0], A[0][0][1], A[0][0][2], A[0][0][3], b0, b1);
                MMA_TF32(C[nt2][1], A[1][0][0], A[1][0][1], A[1][0][2], A[1][0][3], b0, b1);
                MMA_TF32(C[nt2][0], A[0][1][0], A[0][1][1], A[0][1][2], A[0][1][3], b2, b3);
                MMA_TF32(C[nt2][1], A[1][1][0], A[1][1][1], A[1][1][2], A[1][1][3], b2, b3);
            }
        }
        float* ob = out + (size_t)b * (NTOK * DIM);
        #pragma unroll
        for (int nt2 = 0; nt2 < 2; nt2++) {
            const int j0 = (wid * 2 + nt2) * 8 + qd * 2;
            #pragma unroll
            for (int mt = 0; mt < 2; mt++) {
                const int row = mt * 16 + g;   // <= 23, always in range
                *(float2*)(ob + row * DIM + j0) = make_float2(C[nt2][mt][0], C[nt2][mt][1]);
                if (row + 8 < NTOK)
                    *(float2*)(ob + (row + 8) * DIM + j0) = make_float2(C[nt2][mt][2], C[nt2][mt][3]);
            }
        }
    }
}

extern "C" void kernel_launch(void* const* d_in, const int* in_sizes, int n_in,
                              void* d_out, int out_size)
{
    const float* x          = (const float*)d_in[0];
    const float* mask       = (const float*)d_in[1];
    const int*   ids_keep   = (const int*)  d_in[2];
    const float* qkv_w      = (const float*)d_in[3];
    const float* qkv_b      = (const float*)d_in[4];
    const float* proj_w     = (const float*)d_in[5];
    const float* proj_b     = (const float*)d_in[6];
    const float* bias_table = (const float*)d_in[7];
    const int*   rel_index  = (const int*)  d_in[8];

    const int total = 16384 + NWIN * NH * 2 * 4 * 32 * 4;
    prologue<<<(total + 255) / 256, 256>>>(qkv_w, proj_w, mask, ids_keep,
                                           bias_table, rel_index);

    const int smem_bytes = SM_FLOATS * 4;
    cudaFuncSetAttribute(win_attn_kernel,
                         cudaFuncAttributeMaxDynamicSharedMemorySize, smem_bytes);
    win_attn_kernel<<<4096, 256, smem_bytes>>>(x, qkv_b, proj_b, (float*)d_out);
}